// round 3
// baseline (speedup 1.0000x reference)
#include <cuda_runtime.h>
#include <cstdint>

#define NN   10000
#define EE   100000
#define ET   110000
#define FIN  1024
#define HH   3
#define CC   1024
#define HC   3072
#define NCL  460
#define SLOPE 0.2f

// ---------------- device scratch (no allocations allowed) ----------------
__device__ __align__(16) float g_xl[(size_t)NN * HC];      // 122.88 MB
__device__ __align__(16) float g_xr[(size_t)NN * HC];      // 122.88 MB
__device__ __align__(16) float g_hm[(size_t)NN * CC];      // 40.96 MB
__device__ float g_score[ET * HH];           // scores -> alphas in place
__device__ int   g_cnt[NN];
__device__ int   g_off[NN + 1];
__device__ int   g_cur[NN];
__device__ int   g_ssrc[ET];
__device__ int   g_sdst[ET];
__device__ int   g_seid[ET];

// ---------------- CSR build ----------------
__global__ void zero_cnt_kernel() {
    int i = blockIdx.x * blockDim.x + threadIdx.x;
    if (i < NN) g_cnt[i] = 0;
}

// edge_index is int32 (JAX x64 disabled: .astype(jnp.int64) yields int32 on device)
__global__ void hist_kernel(const int* __restrict__ ei) {
    int e = blockIdx.x * blockDim.x + threadIdx.x;
    if (e >= ET) return;
    int d = (e < EE) ? ei[2 * e + 1] : (e - EE);
    atomicAdd(&g_cnt[d], 1);
}

// single-block exclusive scan over g_cnt -> g_off, g_cur
__global__ void scan_kernel() {
    __shared__ int s[1024];
    const int CHUNK = 10; // 1024*10 >= NN
    int t = threadIdx.x;
    int base = t * CHUNK;
    int local[CHUNK];
    int sum = 0;
#pragma unroll
    for (int k = 0; k < CHUNK; k++) {
        int idx = base + k;
        int v = (idx < NN) ? g_cnt[idx] : 0;
        local[k] = sum;
        sum += v;
    }
    s[t] = sum;
    __syncthreads();
    // Hillis-Steele inclusive scan
    for (int off = 1; off < 1024; off <<= 1) {
        int v = (t >= off) ? s[t - off] : 0;
        __syncthreads();
        s[t] += v;
        __syncthreads();
    }
    int cbase = (t > 0) ? s[t - 1] : 0;
#pragma unroll
    for (int k = 0; k < CHUNK; k++) {
        int idx = base + k;
        if (idx < NN) {
            int o = cbase + local[k];
            g_off[idx] = o;
            g_cur[idx] = o;
        }
    }
    if (t == 1023) g_off[NN] = s[1023];
}

__global__ void scatter_kernel(const int* __restrict__ ei) {
    int e = blockIdx.x * blockDim.x + threadIdx.x;
    if (e >= ET) return;
    int sidx, d;
    if (e < EE) { sidx = ei[2 * e]; d = ei[2 * e + 1]; }
    else        { sidx = e - EE;    d = e - EE; }
    int pos = atomicAdd(&g_cur[d], 1);
    g_ssrc[pos] = sidx;
    g_sdst[pos] = d;
    g_seid[pos] = e;
}

// deterministic order: sort each dst segment by original edge id (deg ~ 11)
__global__ void sortseg_kernel() {
    int d = blockIdx.x * blockDim.x + threadIdx.x;
    if (d >= NN) return;
    int b = g_off[d], e2 = g_off[d + 1];
    for (int i = b; i < e2 - 1; i++) {
        int mn = i;
        for (int j = i + 1; j < e2; j++)
            if (g_seid[j] < g_seid[mn]) mn = j;
        if (mn != i) {
            int t0 = g_seid[i]; g_seid[i] = g_seid[mn]; g_seid[mn] = t0;
            int t1 = g_ssrc[i]; g_ssrc[i] = g_ssrc[mn]; g_ssrc[mn] = t1;
        }
    }
}

// ---------------- GEMM: C[M,N] = A[M,K] @ B[K,N] + bias[N] ----------------
// asel: 0 -> A = Aext, 1 -> A = g_hm
// csel: 0 -> C = g_xl, 1 -> C = g_xr, 2 -> C = Cext
__global__ __launch_bounds__(256, 2) void sgemm_bias_kernel(
    const float* __restrict__ Aext, const float* __restrict__ B,
    const float* __restrict__ bias, float* __restrict__ Cext,
    int M, int N, int K, int asel, int csel)
{
    const float* A = asel ? g_hm : Aext;
    float* C = (csel == 0) ? g_xl : (csel == 1) ? g_xr : Cext;

    __shared__ float As[8][128];
    __shared__ float Bs[8][128];

    int tid = threadIdx.x;
    int row0 = blockIdx.y * 128;
    int col0 = blockIdx.x * 128;

    int arow = tid >> 1;           // 0..127
    int akk  = (tid & 1) * 4;      // 0 or 4
    int bkk  = tid >> 5;           // 0..7
    int bcol = (tid & 31) * 4;     // 0..124
    int tx = tid & 15, ty = tid >> 4;

    float acc[8][8];
#pragma unroll
    for (int i = 0; i < 8; i++)
#pragma unroll
        for (int j = 0; j < 8; j++) acc[i][j] = 0.f;

    for (int k0 = 0; k0 < K; k0 += 8) {
        // A tile (K multiple of 8; rows 16B-aligned: K=1024, arrays align(16))
        float4 av = make_float4(0.f, 0.f, 0.f, 0.f);
        if (row0 + arow < M)
            av = *(const float4*)(A + (size_t)(row0 + arow) * K + k0 + akk);
        As[akk + 0][arow] = av.x;
        As[akk + 1][arow] = av.y;
        As[akk + 2][arow] = av.z;
        As[akk + 3][arow] = av.w;
        // B tile (scalar loads: N=460 rows are not 16B aligned)
#pragma unroll
        for (int j = 0; j < 4; j++) {
            int c = col0 + bcol + j;
            Bs[bkk][bcol + j] = (c < N) ? B[(size_t)(k0 + bkk) * N + c] : 0.f;
        }
        __syncthreads();
#pragma unroll
        for (int kk = 0; kk < 8; kk++) {
            float a[8], b[8];
#pragma unroll
            for (int i = 0; i < 8; i++) a[i] = As[kk][ty * 8 + i];
#pragma unroll
            for (int j = 0; j < 8; j++) b[j] = Bs[kk][tx * 8 + j];
#pragma unroll
            for (int i = 0; i < 8; i++)
#pragma unroll
                for (int j = 0; j < 8; j++)
                    acc[i][j] += a[i] * b[j];
        }
        __syncthreads();
    }

#pragma unroll
    for (int i = 0; i < 8; i++) {
        int r = row0 + ty * 8 + i;
        if (r < M) {
#pragma unroll
            for (int j = 0; j < 8; j++) {
                int c = col0 + tx * 8 + j;
                if (c < N) C[(size_t)r * N + c] = acc[i][j] + bias[c];
            }
        }
    }
}

// ---------------- scores: warp per (edge, head) ----------------
__global__ void score_kernel(const float* __restrict__ att) {
    int gw = (blockIdx.x * blockDim.x + threadIdx.x) >> 5;
    int lane = threadIdx.x & 31;
    if (gw >= ET * HH) return;
    int e = gw / 3;
    int h = gw - e * 3;
    int j = g_ssrc[e];
    int i = g_sdst[e];
    const float* xl = g_xl + (size_t)j * HC + h * CC;
    const float* xr = g_xr + (size_t)i * HC + h * CC;
    const float* a  = att + h * CC;
    float acc = 0.f;
#pragma unroll 4
    for (int c = lane; c < CC; c += 32) {
        float v = xl[c] + xr[c];
        v = (v > 0.f) ? v : SLOPE * v;
        acc += v * a[c];
    }
#pragma unroll
    for (int o = 16; o; o >>= 1) acc += __shfl_xor_sync(0xffffffffu, acc, o);
    if (lane == 0) g_score[e * 3 + h] = acc;
}

// ---------------- segment softmax: warp per dst, in-place ----------------
__global__ void softmax_kernel() {
    int warp = threadIdx.x >> 5;
    int lane = threadIdx.x & 31;
    int d = blockIdx.x * (blockDim.x >> 5) + warp;
    if (d >= NN) return;
    int b = g_off[d];
    int n = g_off[d + 1] - b;
#pragma unroll
    for (int h = 0; h < 3; h++) {
        float m = -1e30f;
        for (int k = lane; k < n; k += 32) m = fmaxf(m, g_score[(b + k) * 3 + h]);
#pragma unroll
        for (int o = 16; o; o >>= 1) m = fmaxf(m, __shfl_xor_sync(0xffffffffu, m, o));
        float s = 0.f;
        for (int k = lane; k < n; k += 32) {
            float ex = expf(g_score[(b + k) * 3 + h] - m);
            g_score[(b + k) * 3 + h] = ex;
            s += ex;
        }
#pragma unroll
        for (int o = 16; o; o >>= 1) s += __shfl_xor_sync(0xffffffffu, s, o);
        float inv = 1.f / (s + 1e-16f);
        for (int k = lane; k < n; k += 32) g_score[(b + k) * 3 + h] *= inv;
    }
}

// ---------------- aggregate + head mean + bias: block per dst ----------------
__global__ __launch_bounds__(256) void aggregate_kernel(const float* __restrict__ bias) {
    int d = blockIdx.x;
    int t = threadIdx.x;
    int b = g_off[d];
    int n = g_off[d + 1] - b;
    float acc[12];
#pragma unroll
    for (int q = 0; q < 12; q++) acc[q] = 0.f;
    for (int k = 0; k < n; k++) {
        int j = g_ssrc[b + k];
        const float* xl = g_xl + (size_t)j * HC;
        float a0 = g_score[(b + k) * 3 + 0];
        float a1 = g_score[(b + k) * 3 + 1];
        float a2 = g_score[(b + k) * 3 + 2];
#pragma unroll
        for (int q = 0; q < 4; q++) {
            int c = t + q * 256;
            acc[q]     += a0 * xl[c];
            acc[4 + q] += a1 * xl[CC + c];
            acc[8 + q] += a2 * xl[2 * CC + c];
        }
    }
#pragma unroll
    for (int q = 0; q < 4; q++) {
        int c = t + q * 256;
        g_hm[(size_t)d * CC + c] =
            (acc[q] + acc[4 + q] + acc[8 + q]) * (1.f / 3.f) + bias[c];
    }
}

// ---------------- pass-through copies (kernel, not memcpy nodes) ----------------
__global__ void copy_kernel(const float* __restrict__ a, int na,
                            const float* __restrict__ b, int nb,
                            float* __restrict__ dst) {
    int i = blockIdx.x * blockDim.x + threadIdx.x;
    int total = na + nb;
    if (i >= total) return;
    dst[i] = (i < na) ? a[i] : b[i - na];
}

// ---------------- launch ----------------
extern "C" void kernel_launch(void* const* d_in, const int* in_sizes, int n_in,
                              void* d_out, int out_size)
{
    const float* x      = (const float*)d_in[0];
    const int*   ei     = (const int*)d_in[1];      // int32! (JAX x64 disabled)
    const float* Wl     = (const float*)d_in[2];
    const float* bl     = (const float*)d_in[3];
    const float* Wr     = (const float*)d_in[4];
    const float* br     = (const float*)d_in[5];
    const float* att    = (const float*)d_in[6];
    const float* bias   = (const float*)d_in[7];
    const float* Wfc    = (const float*)d_in[8];
    const float* bfc    = (const float*)d_in[9];
    const float* exps   = (const float*)d_in[10];
    const float* exps_c = (const float*)d_in[11];
    float* out = (float*)d_out;

    // CSR build
    zero_cnt_kernel<<<(NN + 255) / 256, 256>>>();
    hist_kernel<<<(ET + 255) / 256, 256>>>(ei);
    scan_kernel<<<1, 1024>>>();
    scatter_kernel<<<(ET + 255) / 256, 256>>>(ei);
    sortseg_kernel<<<(NN + 127) / 128, 128>>>();

    // xl = x@Wl + bl ; xr = x@Wr + br
    {
        dim3 grid((HC + 127) / 128, (NN + 127) / 128);
        sgemm_bias_kernel<<<grid, 256>>>(x, Wl, bl, nullptr, NN, HC, FIN, 0, 0);
        sgemm_bias_kernel<<<grid, 256>>>(x, Wr, br, nullptr, NN, HC, FIN, 0, 1);
    }

    // attention scores + softmax + aggregation
    {
        long long warps = (long long)ET * HH;
        int blocks = (int)((warps + 7) / 8);
        score_kernel<<<blocks, 256>>>(att);
    }
    softmax_kernel<<<(NN + 7) / 8, 256>>>();
    aggregate_kernel<<<NN, 256>>>(bias);

    // readout: h = hm @ Wfc + bfc -> out[0 : NN*NCL)
    {
        dim3 grid((NCL + 127) / 128, (NN + 127) / 128);
        sgemm_bias_kernel<<<grid, 256>>>(nullptr, Wfc, bfc, out, NN, NCL, CC, 1, 2);
    }

    // pass-throughs: exps, exps_c (copy kernel; no memcpy nodes)
    {
        int na = NN * NCL;
        int nb = 128 * NCL;
        int total = na + nb;
        copy_kernel<<<(total + 255) / 256, 256>>>(exps, na, exps_c, nb,
                                                  out + (size_t)NN * NCL);
    }
}

// round 4
// speedup vs baseline: 1.7733x; 1.7733x over previous
#include <cuda_runtime.h>
#include <cstdint>

#define NN   10000
#define EE   100000
#define ET   110000
#define FIN  1024
#define HH   3
#define CC   1024
#define HC   3072
#define NCL  460
#define SLOPE 0.2f

// ---------------- device scratch (no allocations allowed) ----------------
__device__ __align__(16) float g_xl[(size_t)NN * HC];      // 122.88 MB
__device__ __align__(16) float g_xr[(size_t)NN * HC];      // 122.88 MB
__device__ __align__(16) float g_hm[(size_t)NN * CC];      // 40.96 MB
__device__ float g_score[ET * HH];
__device__ int   g_cnt[NN];
__device__ int   g_off[NN + 1];
__device__ int   g_cur[NN];
__device__ int   g_ssrc[ET];
__device__ int   g_sdst[ET];
__device__ int   g_seid[ET];

// ---------------- CSR build ----------------
__global__ void zero_cnt_kernel() {
    int i = blockIdx.x * blockDim.x + threadIdx.x;
    if (i < NN) g_cnt[i] = 0;
}

__global__ void hist_kernel(const int* __restrict__ ei) {
    int e = blockIdx.x * blockDim.x + threadIdx.x;
    if (e >= ET) return;
    int d = (e < EE) ? ei[2 * e + 1] : (e - EE);
    atomicAdd(&g_cnt[d], 1);
}

__global__ void scan_kernel() {
    __shared__ int s[1024];
    const int CHUNK = 10;
    int t = threadIdx.x;
    int base = t * CHUNK;
    int local[CHUNK];
    int sum = 0;
#pragma unroll
    for (int k = 0; k < CHUNK; k++) {
        int idx = base + k;
        int v = (idx < NN) ? g_cnt[idx] : 0;
        local[k] = sum;
        sum += v;
    }
    s[t] = sum;
    __syncthreads();
    for (int off = 1; off < 1024; off <<= 1) {
        int v = (t >= off) ? s[t - off] : 0;
        __syncthreads();
        s[t] += v;
        __syncthreads();
    }
    int cbase = (t > 0) ? s[t - 1] : 0;
#pragma unroll
    for (int k = 0; k < CHUNK; k++) {
        int idx = base + k;
        if (idx < NN) {
            int o = cbase + local[k];
            g_off[idx] = o;
            g_cur[idx] = o;
        }
    }
    if (t == 1023) g_off[NN] = s[1023];
}

__global__ void scatter_kernel(const int* __restrict__ ei) {
    int e = blockIdx.x * blockDim.x + threadIdx.x;
    if (e >= ET) return;
    int sidx, d;
    if (e < EE) { sidx = ei[2 * e]; d = ei[2 * e + 1]; }
    else        { sidx = e - EE;    d = e - EE; }
    int pos = atomicAdd(&g_cur[d], 1);
    g_ssrc[pos] = sidx;
    g_sdst[pos] = d;
    g_seid[pos] = e;
}

__global__ void sortseg_kernel() {
    int d = blockIdx.x * blockDim.x + threadIdx.x;
    if (d >= NN) return;
    int b = g_off[d], e2 = g_off[d + 1];
    for (int i = b; i < e2 - 1; i++) {
        int mn = i;
        for (int j = i + 1; j < e2; j++)
            if (g_seid[j] < g_seid[mn]) mn = j;
        if (mn != i) {
            int t0 = g_seid[i]; g_seid[i] = g_seid[mn]; g_seid[mn] = t0;
            int t1 = g_ssrc[i]; g_ssrc[i] = g_ssrc[mn]; g_ssrc[mn] = t1;
        }
    }
}

// ---------------- tf32 tensor-core GEMM ----------------
// C[M,N] = A[M,K] @ B[K,N] + bias[N]
// Block tile 128x128, 8 warps (2x4), warp tile 64x32, K-stage 16, cp.async db.
// asel: 0 -> A = Aext, 1 -> A = g_hm ; csel: 0 -> g_xl, 1 -> g_xr, 2 -> Cext

#define AS_STRIDE 20    // 16 + 4 pad (floats)
#define BS_STRIDE 136   // 128 + 8 pad (floats)

__device__ __forceinline__ void cp16(uint32_t saddr, const void* g, bool pred) {
    int sz = pred ? 16 : 0;
    asm volatile("cp.async.cg.shared.global [%0], [%1], 16, %2;\n"
                 :: "r"(saddr), "l"(g), "r"(sz));
}
__device__ __forceinline__ uint32_t f2tf32(float f) {
    uint32_t u;
    asm("cvt.rna.tf32.f32 %0, %1;\n" : "=r"(u) : "f"(f));
    return u;
}

__global__ __launch_bounds__(256) void gemm_tf32_kernel(
    const float* __restrict__ Aext, const float* __restrict__ B,
    const float* __restrict__ bias, float* __restrict__ Cext,
    int M, int N, int K, int asel, int csel)
{
    const float* A = asel ? g_hm : Aext;
    float* C = (csel == 0) ? g_xl : (csel == 1) ? g_xr : Cext;

    __shared__ float As[2][128 * AS_STRIDE];
    __shared__ float Bs[2][16 * BS_STRIDE];

    int tid  = threadIdx.x;
    int lane = tid & 31;
    int warp = tid >> 5;
    int wm = warp >> 2;          // 0..1
    int wn = warp & 3;           // 0..3
    int lr = lane >> 2;          // 0..7
    int lc = lane & 3;           // 0..3

    int row0 = blockIdx.y * 128;
    int col0 = blockIdx.x * 128;

    // A-load map: thread -> (row = tid>>1, kcol = (tid&1)*8), two float4
    int a_r  = tid >> 1;
    int a_c  = (tid & 1) * 8;
    bool a_ok = (row0 + a_r) < M;
    const float* a_g0 = A + (size_t)(row0 + a_r) * K + a_c;

    // B-load map: thread -> (krow = tid>>4, ncol = (tid&15)*8), two float4
    int b_k  = tid >> 4;
    int b_n  = (tid & 15) * 8;
    bool b_ok0 = (col0 + b_n) < N;
    bool b_ok1 = (col0 + b_n + 4) < N;
    const float* b_g0 = B + (size_t)b_k * N + col0 + b_n;

    float acc[4][4][4];
#pragma unroll
    for (int i = 0; i < 4; i++)
#pragma unroll
        for (int j = 0; j < 4; j++)
#pragma unroll
            for (int r = 0; r < 4; r++) acc[i][j][r] = 0.f;

    int kIters = K / 16;

    // prologue: stage 0
    {
        uint32_t sa = (uint32_t)__cvta_generic_to_shared(&As[0][a_r * AS_STRIDE + a_c]);
        cp16(sa,      a_g0,     a_ok);
        cp16(sa + 16, a_g0 + 4, a_ok);
        uint32_t sb = (uint32_t)__cvta_generic_to_shared(&Bs[0][b_k * BS_STRIDE + b_n]);
        cp16(sb,      b_g0,     b_ok0);
        cp16(sb + 16, b_g0 + 4, b_ok1);
        asm volatile("cp.async.commit_group;\n");
        asm volatile("cp.async.wait_group 0;\n");
        __syncthreads();
    }

    for (int it = 0; it < kIters; it++) {
        int cur = it & 1;
        int nxt = cur ^ 1;
        if (it + 1 < kIters) {
            int k0 = (it + 1) * 16;
            uint32_t sa = (uint32_t)__cvta_generic_to_shared(&As[nxt][a_r * AS_STRIDE + a_c]);
            cp16(sa,      a_g0 + k0,     a_ok);
            cp16(sa + 16, a_g0 + k0 + 4, a_ok);
            uint32_t sb = (uint32_t)__cvta_generic_to_shared(&Bs[nxt][b_k * BS_STRIDE + b_n]);
            const float* bg = b_g0 + (size_t)k0 * N;
            cp16(sb,      bg,     b_ok0);
            cp16(sb + 16, bg + 4, b_ok1);
            asm volatile("cp.async.commit_group;\n");
        }

        const float* as = As[cur];
        const float* bs = Bs[cur];
#pragma unroll
        for (int ks = 0; ks < 16; ks += 8) {
            uint32_t a[4][4], b[4][2];
#pragma unroll
            for (int mi = 0; mi < 4; mi++) {
                int mb = (wm * 64 + mi * 16 + lr) * AS_STRIDE + ks + lc;
                a[mi][0] = f2tf32(as[mb]);
                a[mi][1] = f2tf32(as[mb + 8 * AS_STRIDE]);
                a[mi][2] = f2tf32(as[mb + 4]);
                a[mi][3] = f2tf32(as[mb + 8 * AS_STRIDE + 4]);
            }
#pragma unroll
            for (int ni = 0; ni < 4; ni++) {
                int nb = (ks + lc) * BS_STRIDE + wn * 32 + ni * 8 + lr;
                b[ni][0] = f2tf32(bs[nb]);
                b[ni][1] = f2tf32(bs[nb + 4 * BS_STRIDE]);
            }
#pragma unroll
            for (int mi = 0; mi < 4; mi++)
#pragma unroll
                for (int ni = 0; ni < 4; ni++) {
                    float* d = acc[mi][ni];
                    asm volatile(
                        "mma.sync.aligned.m16n8k8.row.col.f32.tf32.tf32.f32 "
                        "{%0,%1,%2,%3}, {%4,%5,%6,%7}, {%8,%9}, {%0,%1,%2,%3};\n"
                        : "+f"(d[0]), "+f"(d[1]), "+f"(d[2]), "+f"(d[3])
                        : "r"(a[mi][0]), "r"(a[mi][1]), "r"(a[mi][2]), "r"(a[mi][3]),
                          "r"(b[ni][0]), "r"(b[ni][1]));
                }
        }
        if (it + 1 < kIters)
            asm volatile("cp.async.wait_group 0;\n");
        __syncthreads();
    }

    // epilogue: D fragment -> row = lr (+8), col = 2*lc (+1)
#pragma unroll
    for (int mi = 0; mi < 4; mi++) {
#pragma unroll
        for (int ni = 0; ni < 4; ni++) {
            int r0 = row0 + wm * 64 + mi * 16 + lr;
            int c  = col0 + wn * 32 + ni * 8 + 2 * lc;
            if (c < N) {
                float bv0 = bias[c], bv1 = bias[c + 1];
                if (r0 < M) {
                    float2 v = make_float2(acc[mi][ni][0] + bv0, acc[mi][ni][1] + bv1);
                    *(float2*)(C + (size_t)r0 * N + c) = v;
                }
                if (r0 + 8 < M) {
                    float2 v = make_float2(acc[mi][ni][2] + bv0, acc[mi][ni][3] + bv1);
                    *(float2*)(C + (size_t)(r0 + 8) * N + c) = v;
                }
            }
        }
    }
}

// ---------------- scores: warp per (edge, head) ----------------
__global__ void score_kernel(const float* __restrict__ att) {
    int gw = (blockIdx.x * blockDim.x + threadIdx.x) >> 5;
    int lane = threadIdx.x & 31;
    if (gw >= ET * HH) return;
    int e = gw / 3;
    int h = gw - e * 3;
    int j = g_ssrc[e];
    int i = g_sdst[e];
    const float* xl = g_xl + (size_t)j * HC + h * CC;
    const float* xr = g_xr + (size_t)i * HC + h * CC;
    const float* a  = att + h * CC;
    float acc = 0.f;
#pragma unroll 4
    for (int c = lane; c < CC; c += 32) {
        float v = xl[c] + xr[c];
        v = (v > 0.f) ? v : SLOPE * v;
        acc += v * a[c];
    }
#pragma unroll
    for (int o = 16; o; o >>= 1) acc += __shfl_xor_sync(0xffffffffu, acc, o);
    if (lane == 0) g_score[e * 3 + h] = acc;
}

// ---------------- segment softmax: warp per dst, in-place ----------------
__global__ void softmax_kernel() {
    int warp = threadIdx.x >> 5;
    int lane = threadIdx.x & 31;
    int d = blockIdx.x * (blockDim.x >> 5) + warp;
    if (d >= NN) return;
    int b = g_off[d];
    int n = g_off[d + 1] - b;
#pragma unroll
    for (int h = 0; h < 3; h++) {
        float m = -1e30f;
        for (int k = lane; k < n; k += 32) m = fmaxf(m, g_score[(b + k) * 3 + h]);
#pragma unroll
        for (int o = 16; o; o >>= 1) m = fmaxf(m, __shfl_xor_sync(0xffffffffu, m, o));
        float s = 0.f;
        for (int k = lane; k < n; k += 32) {
            float ex = expf(g_score[(b + k) * 3 + h] - m);
            g_score[(b + k) * 3 + h] = ex;
            s += ex;
        }
#pragma unroll
        for (int o = 16; o; o >>= 1) s += __shfl_xor_sync(0xffffffffu, s, o);
        float inv = 1.f / (s + 1e-16f);
        for (int k = lane; k < n; k += 32) g_score[(b + k) * 3 + h] *= inv;
    }
}

// ---------------- aggregate + head mean + bias: block per dst ----------------
__global__ __launch_bounds__(256) void aggregate_kernel(const float* __restrict__ bias) {
    int d = blockIdx.x;
    int t = threadIdx.x;
    int b = g_off[d];
    int n = g_off[d + 1] - b;
    float acc[12];
#pragma unroll
    for (int q = 0; q < 12; q++) acc[q] = 0.f;
    for (int k = 0; k < n; k++) {
        int j = g_ssrc[b + k];
        const float* xl = g_xl + (size_t)j * HC;
        float a0 = g_score[(b + k) * 3 + 0];
        float a1 = g_score[(b + k) * 3 + 1];
        float a2 = g_score[(b + k) * 3 + 2];
#pragma unroll
        for (int q = 0; q < 4; q++) {
            int c = t + q * 256;
            acc[q]     += a0 * xl[c];
            acc[4 + q] += a1 * xl[CC + c];
            acc[8 + q] += a2 * xl[2 * CC + c];
        }
    }
#pragma unroll
    for (int q = 0; q < 4; q++) {
        int c = t + q * 256;
        g_hm[(size_t)d * CC + c] =
            (acc[q] + acc[4 + q] + acc[8 + q]) * (1.f / 3.f) + bias[c];
    }
}

// ---------------- pass-through copies ----------------
__global__ void copy_kernel(const float* __restrict__ a, int na,
                            const float* __restrict__ b, int nb,
                            float* __restrict__ dst) {
    int i = blockIdx.x * blockDim.x + threadIdx.x;
    int total = na + nb;
    if (i >= total) return;
    dst[i] = (i < na) ? a[i] : b[i - na];
}

// ---------------- launch ----------------
extern "C" void kernel_launch(void* const* d_in, const int* in_sizes, int n_in,
                              void* d_out, int out_size)
{
    const float* x      = (const float*)d_in[0];
    const int*   ei     = (const int*)d_in[1];      // int32 (JAX x64 disabled)
    const float* Wl     = (const float*)d_in[2];
    const float* bl     = (const float*)d_in[3];
    const float* Wr     = (const float*)d_in[4];
    const float* br     = (const float*)d_in[5];
    const float* att    = (const float*)d_in[6];
    const float* bias   = (const float*)d_in[7];
    const float* Wfc    = (const float*)d_in[8];
    const float* bfc    = (const float*)d_in[9];
    const float* exps   = (const float*)d_in[10];
    const float* exps_c = (const float*)d_in[11];
    float* out = (float*)d_out;

    // CSR build
    zero_cnt_kernel<<<(NN + 255) / 256, 256>>>();
    hist_kernel<<<(ET + 255) / 256, 256>>>(ei);
    scan_kernel<<<1, 1024>>>();
    scatter_kernel<<<(ET + 255) / 256, 256>>>(ei);
    sortseg_kernel<<<(NN + 127) / 128, 128>>>();

    // xl = x@Wl + bl ; xr = x@Wr + br  (tf32 tensor cores)
    {
        dim3 grid((HC + 127) / 128, (NN + 127) / 128);
        gemm_tf32_kernel<<<grid, 256>>>(x, Wl, bl, nullptr, NN, HC, FIN, 0, 0);
        gemm_tf32_kernel<<<grid, 256>>>(x, Wr, br, nullptr, NN, HC, FIN, 0, 1);
    }

    // attention scores + softmax + aggregation
    {
        long long warps = (long long)ET * HH;
        int blocks = (int)((warps + 7) / 8);
        score_kernel<<<blocks, 256>>>(att);
    }
    softmax_kernel<<<(NN + 7) / 8, 256>>>();
    aggregate_kernel<<<NN, 256>>>(bias);

    // readout: h = hm @ Wfc + bfc
    {
        dim3 grid((NCL + 127) / 128, (NN + 127) / 128);
        gemm_tf32_kernel<<<grid, 256>>>(nullptr, Wfc, bfc, out, NN, NCL, CC, 1, 2);
    }

    // pass-throughs
    {
        int na = NN * NCL;
        int nb = 128 * NCL;
        int total = na + nb;
        copy_kernel<<<(total + 255) / 256, 256>>>(exps, na, exps_c, nb,
                                                  out + (size_t)NN * NCL);
    }
}

// round 5
// speedup vs baseline: 2.8263x; 1.5938x over previous
#include <cuda_runtime.h>
#include <cstdint>

#define NN   10000
#define EE   100000
#define ET   110000
#define FIN  1024
#define HH   3
#define CC   1024
#define HC   3072
#define NCL  460
#define SLOPE 0.2f

// ---------------- device scratch ----------------
__device__ __align__(16) float g_xl[(size_t)NN * HC];
__device__ __align__(16) float g_xr[(size_t)NN * HC];
__device__ __align__(16) float g_hm[(size_t)NN * CC];      // tf32-rounded by aggregate
__device__ __align__(16) float g_xt[(size_t)NN * FIN];     // tf32-rounded x
__device__ __align__(16) float g_wl[(size_t)FIN * HC];     // tf32-rounded Wl
__device__ __align__(16) float g_wr[(size_t)FIN * HC];     // tf32-rounded Wr
__device__ __align__(16) float g_wfc[(size_t)CC * NCL];    // tf32-rounded Wfc
__device__ float g_score[ET * HH];
__device__ int   g_cnt[NN];
__device__ int   g_off[NN + 1];
__device__ int   g_cur[NN];
__device__ int   g_ssrc[ET];
__device__ int   g_seid[ET];

__device__ __forceinline__ uint32_t f2tf32(float f) {
    uint32_t u;
    asm("cvt.rna.tf32.f32 %0, %1;\n" : "=r"(u) : "f"(f));
    return u;
}
__device__ __forceinline__ float roundtf(float f) { return __uint_as_float(f2tf32(f)); }

// ---------------- tf32 pre-rounding ----------------
__global__ void round_kernel(const float* __restrict__ in, int n4, int dsel) {
    float* dst = (dsel == 0) ? g_xt : (dsel == 1) ? g_wl : (dsel == 2) ? g_wr : g_wfc;
    int i = blockIdx.x * blockDim.x + threadIdx.x;
    if (i >= n4) return;
    float4 v = ((const float4*)in)[i];
    v.x = roundtf(v.x); v.y = roundtf(v.y); v.z = roundtf(v.z); v.w = roundtf(v.w);
    ((float4*)dst)[i] = v;
}

// ---------------- CSR build ----------------
__global__ void zero_cnt_kernel() {
    int i = blockIdx.x * blockDim.x + threadIdx.x;
    if (i < NN) g_cnt[i] = 0;
}

__global__ void hist_kernel(const int* __restrict__ ei) {
    int e = blockIdx.x * blockDim.x + threadIdx.x;
    if (e >= ET) return;
    int d = (e < EE) ? ei[2 * e + 1] : (e - EE);
    atomicAdd(&g_cnt[d], 1);
}

__global__ void scan_kernel() {
    __shared__ int s[1024];
    const int CHUNK = 10;
    int t = threadIdx.x;
    int base = t * CHUNK;
    int local[CHUNK];
    int sum = 0;
#pragma unroll
    for (int k = 0; k < CHUNK; k++) {
        int idx = base + k;
        int v = (idx < NN) ? g_cnt[idx] : 0;
        local[k] = sum;
        sum += v;
    }
    s[t] = sum;
    __syncthreads();
    for (int off = 1; off < 1024; off <<= 1) {
        int v = (t >= off) ? s[t - off] : 0;
        __syncthreads();
        s[t] += v;
        __syncthreads();
    }
    int cbase = (t > 0) ? s[t - 1] : 0;
#pragma unroll
    for (int k = 0; k < CHUNK; k++) {
        int idx = base + k;
        if (idx < NN) {
            int o = cbase + local[k];
            g_off[idx] = o;
            g_cur[idx] = o;
        }
    }
    if (t == 1023) g_off[NN] = s[1023];
}

__global__ void scatter_kernel(const int* __restrict__ ei) {
    int e = blockIdx.x * blockDim.x + threadIdx.x;
    if (e >= ET) return;
    int sidx, d;
    if (e < EE) { sidx = ei[2 * e]; d = ei[2 * e + 1]; }
    else        { sidx = e - EE;    d = e - EE; }
    int pos = atomicAdd(&g_cur[d], 1);
    g_ssrc[pos] = sidx;
    g_seid[pos] = e;
}

__global__ void sortseg_kernel() {
    int d = blockIdx.x * blockDim.x + threadIdx.x;
    if (d >= NN) return;
    int b = g_off[d], e2 = g_off[d + 1];
    for (int i = b; i < e2 - 1; i++) {
        int mn = i;
        for (int j = i + 1; j < e2; j++)
            if (g_seid[j] < g_seid[mn]) mn = j;
        if (mn != i) {
            int t0 = g_seid[i]; g_seid[i] = g_seid[mn]; g_seid[mn] = t0;
            int t1 = g_ssrc[i]; g_ssrc[i] = g_ssrc[mn]; g_ssrc[mn] = t1;
        }
    }
}

// ---------------- tf32 tensor-core GEMM (inputs pre-rounded) ----------------
// mode 0: A=g_xt [NN,FIN], B = z? g_wr : g_wl, bias = z? br : bl, C = z? g_xr : g_xl, N=HC
// mode 1: A=g_hm [NN,CC],  B = g_wfc, bias = bfc, C = Cext, N=NCL
#define AS_STRIDE 20
#define BS_STRIDE 136

__device__ __forceinline__ void cp16(uint32_t saddr, const void* g, bool pred) {
    int sz = pred ? 16 : 0;
    asm volatile("cp.async.cg.shared.global [%0], [%1], 16, %2;\n"
                 :: "r"(saddr), "l"(g), "r"(sz));
}

__global__ __launch_bounds__(256) void gemm_tc_kernel(
    const float* __restrict__ bl, const float* __restrict__ br,
    const float* __restrict__ bfc, float* __restrict__ Cext, int mode)
{
    const float* A;
    const float* B;
    const float* bias;
    float* C;
    int M = NN, N, K;
    if (mode == 0) {
        int z = blockIdx.z;
        A = g_xt; B = z ? g_wr : g_wl; bias = z ? br : bl; C = z ? g_xr : g_xl;
        N = HC; K = FIN;
    } else {
        A = g_hm; B = g_wfc; bias = bfc; C = Cext;
        N = NCL; K = CC;
    }

    __shared__ float As[2][128 * AS_STRIDE];
    __shared__ float Bs[2][16 * BS_STRIDE];

    int tid  = threadIdx.x;
    int lane = tid & 31;
    int warp = tid >> 5;
    int wm = warp >> 2;
    int wn = warp & 3;
    int lr = lane >> 2;
    int lc = lane & 3;

    int row0 = blockIdx.y * 128;
    int col0 = blockIdx.x * 128;

    int a_r  = tid >> 1;
    int a_c  = (tid & 1) * 8;
    bool a_ok = (row0 + a_r) < M;
    const float* a_g0 = A + (size_t)(row0 + a_r) * K + a_c;

    int b_k  = tid >> 4;
    int b_n  = (tid & 15) * 8;
    bool b_ok0 = (col0 + b_n) < N;
    bool b_ok1 = (col0 + b_n + 4) < N;
    const float* b_g0 = B + (size_t)b_k * N + col0 + b_n;

    float acc[4][4][4];
#pragma unroll
    for (int i = 0; i < 4; i++)
#pragma unroll
        for (int j = 0; j < 4; j++)
#pragma unroll
            for (int r = 0; r < 4; r++) acc[i][j][r] = 0.f;

    int kIters = K / 16;

    {
        uint32_t sa = (uint32_t)__cvta_generic_to_shared(&As[0][a_r * AS_STRIDE + a_c]);
        cp16(sa,      a_g0,     a_ok);
        cp16(sa + 16, a_g0 + 4, a_ok);
        uint32_t sb = (uint32_t)__cvta_generic_to_shared(&Bs[0][b_k * BS_STRIDE + b_n]);
        cp16(sb,      b_g0,     b_ok0);
        cp16(sb + 16, b_g0 + 4, b_ok1);
        asm volatile("cp.async.commit_group;\n");
        asm volatile("cp.async.wait_group 0;\n");
        __syncthreads();
    }

    for (int it = 0; it < kIters; it++) {
        int cur = it & 1;
        int nxt = cur ^ 1;
        if (it + 1 < kIters) {
            int k0 = (it + 1) * 16;
            uint32_t sa = (uint32_t)__cvta_generic_to_shared(&As[nxt][a_r * AS_STRIDE + a_c]);
            cp16(sa,      a_g0 + k0,     a_ok);
            cp16(sa + 16, a_g0 + k0 + 4, a_ok);
            uint32_t sb = (uint32_t)__cvta_generic_to_shared(&Bs[nxt][b_k * BS_STRIDE + b_n]);
            const float* bg = b_g0 + (size_t)k0 * N;
            cp16(sb,      bg,     b_ok0);
            cp16(sb + 16, bg + 4, b_ok1);
            asm volatile("cp.async.commit_group;\n");
        }

        const uint32_t* as = (const uint32_t*)As[cur];
        const uint32_t* bs = (const uint32_t*)Bs[cur];
#pragma unroll
        for (int ks = 0; ks < 16; ks += 8) {
            uint32_t a[4][4], b[4][2];
#pragma unroll
            for (int mi = 0; mi < 4; mi++) {
                int mb = (wm * 64 + mi * 16 + lr) * AS_STRIDE + ks + lc;
                a[mi][0] = as[mb];
                a[mi][1] = as[mb + 8 * AS_STRIDE];
                a[mi][2] = as[mb + 4];
                a[mi][3] = as[mb + 8 * AS_STRIDE + 4];
            }
#pragma unroll
            for (int ni = 0; ni < 4; ni++) {
                int nb = (ks + lc) * BS_STRIDE + wn * 32 + ni * 8 + lr;
                b[ni][0] = bs[nb];
                b[ni][1] = bs[nb + 4 * BS_STRIDE];
            }
#pragma unroll
            for (int mi = 0; mi < 4; mi++)
#pragma unroll
                for (int ni = 0; ni < 4; ni++) {
                    float* d = acc[mi][ni];
                    asm volatile(
                        "mma.sync.aligned.m16n8k8.row.col.f32.tf32.tf32.f32 "
                        "{%0,%1,%2,%3}, {%4,%5,%6,%7}, {%8,%9}, {%0,%1,%2,%3};\n"
                        : "+f"(d[0]), "+f"(d[1]), "+f"(d[2]), "+f"(d[3])
                        : "r"(a[mi][0]), "r"(a[mi][1]), "r"(a[mi][2]), "r"(a[mi][3]),
                          "r"(b[ni][0]), "r"(b[ni][1]));
                }
        }
        if (it + 1 < kIters)
            asm volatile("cp.async.wait_group 0;\n");
        __syncthreads();
    }

#pragma unroll
    for (int mi = 0; mi < 4; mi++) {
#pragma unroll
        for (int ni = 0; ni < 4; ni++) {
            int r0 = row0 + wm * 64 + mi * 16 + lr;
            int c  = col0 + wn * 32 + ni * 8 + 2 * lc;
            if (c < N) {
                float bv0 = bias[c], bv1 = bias[c + 1];
                if (r0 < M) {
                    float2 v = make_float2(acc[mi][ni][0] + bv0, acc[mi][ni][1] + bv1);
                    *(float2*)(C + (size_t)r0 * N + c) = v;
                }
                if (r0 + 8 < M) {
                    float2 v = make_float2(acc[mi][ni][2] + bv0, acc[mi][ni][3] + bv1);
                    *(float2*)(C + (size_t)(r0 + 8) * N + c) = v;
                }
            }
        }
    }
}

// ---------------- scores: warp per (edge, head), float4 ----------------
__global__ void score_kernel(const float* __restrict__ att) {
    int gw = (blockIdx.x * blockDim.x + threadIdx.x) >> 5;
    int lane = threadIdx.x & 31;
    if (gw >= ET * HH) return;
    int e = gw / 3;
    int h = gw - e * 3;
    int j = g_ssrc[e];
    int i = g_off[0] == 0 ? 0 : 0;  // placeholder no-op
    // dst index for edge e: find via seid? we stored sorted arrays; dst implied by segment.
    // Use binary search-free: we saved dst implicitly; need explicit dst array read.
    (void)i;
    int d = 0;
    // recover dst: edges are stored sorted by dst; g_off gives segment bounds.
    // Instead of search, read from g_seid? We removed g_sdst; restore via search:
    // binary search over g_off for e's position.
    {
        int lo = 0, hi = NN;
        while (lo + 1 < hi) {
            int mid = (lo + hi) >> 1;
            if (g_off[mid] <= e) lo = mid; else hi = mid;
        }
        d = lo;
    }
    const float4* xl4 = (const float4*)(g_xl + (size_t)j * HC + h * CC);
    const float4* xr4 = (const float4*)(g_xr + (size_t)d * HC + h * CC);
    const float4* a4  = (const float4*)(att + h * CC);
    float acc = 0.f;
#pragma unroll 2
    for (int c = lane; c < 256; c += 32) {
        float4 l = xl4[c];
        float4 r = xr4[c];
        float4 a = a4[c];
        float v0 = l.x + r.x; v0 = (v0 > 0.f) ? v0 : SLOPE * v0;
        float v1 = l.y + r.y; v1 = (v1 > 0.f) ? v1 : SLOPE * v1;
        float v2 = l.z + r.z; v2 = (v2 > 0.f) ? v2 : SLOPE * v2;
        float v3 = l.w + r.w; v3 = (v3 > 0.f) ? v3 : SLOPE * v3;
        acc += v0 * a.x + v1 * a.y + v2 * a.z + v3 * a.w;
    }
#pragma unroll
    for (int o = 16; o; o >>= 1) acc += __shfl_xor_sync(0xffffffffu, acc, o);
    if (lane == 0) g_score[e * 3 + h] = acc;
}

// ---------------- segment softmax: warp per dst ----------------
__global__ void softmax_kernel() {
    int warp = threadIdx.x >> 5;
    int lane = threadIdx.x & 31;
    int d = blockIdx.x * (blockDim.x >> 5) + warp;
    if (d >= NN) return;
    int b = g_off[d];
    int n = g_off[d + 1] - b;
#pragma unroll
    for (int h = 0; h < 3; h++) {
        float m = -1e30f;
        for (int k = lane; k < n; k += 32) m = fmaxf(m, g_score[(b + k) * 3 + h]);
#pragma unroll
        for (int o = 16; o; o >>= 1) m = fmaxf(m, __shfl_xor_sync(0xffffffffu, m, o));
        float s = 0.f;
        for (int k = lane; k < n; k += 32) {
            float ex = expf(g_score[(b + k) * 3 + h] - m);
            g_score[(b + k) * 3 + h] = ex;
            s += ex;
        }
#pragma unroll
        for (int o = 16; o; o >>= 1) s += __shfl_xor_sync(0xffffffffu, s, o);
        float inv = 1.f / (s + 1e-16f);
        for (int k = lane; k < n; k += 32) g_score[(b + k) * 3 + h] *= inv;
    }
}

// ---------------- aggregate + head mean + bias (float4, writes tf32-rounded hm) ----------------
__global__ __launch_bounds__(256) void aggregate_kernel(const float* __restrict__ bias) {
    int d = blockIdx.x;
    int t = threadIdx.x;            // col group: 4 floats at 4*t
    int b = g_off[d];
    int n = g_off[d + 1] - b;
    float4 acc0 = make_float4(0.f, 0.f, 0.f, 0.f);
    float4 acc1 = acc0, acc2 = acc0;
    for (int k = 0; k < n; k++) {
        int j = g_ssrc[b + k];
        const float4* xl4 = (const float4*)(g_xl + (size_t)j * HC);
        float a0 = g_score[(b + k) * 3 + 0];
        float a1 = g_score[(b + k) * 3 + 1];
        float a2 = g_score[(b + k) * 3 + 2];
        float4 v0 = xl4[t];
        float4 v1 = xl4[256 + t];
        float4 v2 = xl4[512 + t];
        acc0.x += a0 * v0.x; acc0.y += a0 * v0.y; acc0.z += a0 * v0.z; acc0.w += a0 * v0.w;
        acc1.x += a1 * v1.x; acc1.y += a1 * v1.y; acc1.z += a1 * v1.z; acc1.w += a1 * v1.w;
        acc2.x += a2 * v2.x; acc2.y += a2 * v2.y; acc2.z += a2 * v2.z; acc2.w += a2 * v2.w;
    }
    float4 bv = ((const float4*)bias)[t];
    float4 o;
    o.x = roundtf((acc0.x + acc1.x + acc2.x) * (1.f / 3.f) + bv.x);
    o.y = roundtf((acc0.y + acc1.y + acc2.y) * (1.f / 3.f) + bv.y);
    o.z = roundtf((acc0.z + acc1.z + acc2.z) * (1.f / 3.f) + bv.z);
    o.w = roundtf((acc0.w + acc1.w + acc2.w) * (1.f / 3.f) + bv.w);
    ((float4*)(g_hm + (size_t)d * CC))[t] = o;
}

// ---------------- pass-through copies (float4) ----------------
__global__ void copy_kernel(const float* __restrict__ a, int na4,
                            const float* __restrict__ b, int nb4,
                            float* __restrict__ dst) {
    int i = blockIdx.x * blockDim.x + threadIdx.x;
    if (i >= na4 + nb4) return;
    float4 v = (i < na4) ? ((const float4*)a)[i] : ((const float4*)b)[i - na4];
    ((float4*)dst)[i] = v;
}

// ---------------- launch ----------------
extern "C" void kernel_launch(void* const* d_in, const int* in_sizes, int n_in,
                              void* d_out, int out_size)
{
    const float* x      = (const float*)d_in[0];
    const int*   ei     = (const int*)d_in[1];
    const float* Wl     = (const float*)d_in[2];
    const float* bl     = (const float*)d_in[3];
    const float* Wr     = (const float*)d_in[4];
    const float* br     = (const float*)d_in[5];
    const float* att    = (const float*)d_in[6];
    const float* bias   = (const float*)d_in[7];
    const float* Wfc    = (const float*)d_in[8];
    const float* bfc    = (const float*)d_in[9];
    const float* exps   = (const float*)d_in[10];
    const float* exps_c = (const float*)d_in[11];
    float* out = (float*)d_out;

    // pre-round inputs to tf32 bit patterns (launches 1-4)
    round_kernel<<<(NN * FIN / 4 + 255) / 256, 256>>>(x,   NN * FIN / 4, 0);
    round_kernel<<<(FIN * HC / 4 + 255) / 256, 256>>>(Wl,  FIN * HC / 4, 1);
    round_kernel<<<(FIN * HC / 4 + 255) / 256, 256>>>(Wr,  FIN * HC / 4, 2);
    round_kernel<<<(CC * NCL / 4 + 255) / 256, 256>>>(Wfc, CC * NCL / 4, 3);

    zero_cnt_kernel<<<(NN + 255) / 256, 256>>>();   // launch 5

    // fused projection GEMMs (launch 6 — ncu capture target)
    {
        dim3 grid((HC + 127) / 128, (NN + 127) / 128, 2);
        gemm_tc_kernel<<<grid, 256>>>(bl, br, bfc, out, 0);
    }

    // CSR build
    hist_kernel<<<(ET + 255) / 256, 256>>>(ei);
    scan_kernel<<<1, 1024>>>();
    scatter_kernel<<<(ET + 255) / 256, 256>>>(ei);
    sortseg_kernel<<<(NN + 127) / 128, 128>>>();

    // attention
    {
        long long warps = (long long)ET * HH;
        int blocks = (int)((warps + 7) / 8);
        score_kernel<<<blocks, 256>>>(att);
    }
    softmax_kernel<<<(NN + 7) / 8, 256>>>();
    aggregate_kernel<<<NN, 256>>>(bias);

    // readout
    {
        dim3 grid((NCL + 127) / 128, (NN + 127) / 128, 1);
        gemm_tc_kernel<<<grid, 256>>>(bl, br, bfc, out, 1);
    }

    // pass-throughs
    {
        int na4 = NN * NCL / 4;
        int nb4 = 128 * NCL / 4;
        copy_kernel<<<(na4 + nb4 + 255) / 256, 256>>>(exps, na4, exps_c, nb4,
                                                      out + (size_t)NN * NCL);
    }
}